// round 1
// baseline (speedup 1.0000x reference)
#include <cuda_runtime.h>
#include <cstdint>

#define N_NODES 12288
#define H_DIM   128
#define E_EDGES 393216
#define NEGVAL  (-1000000000.0f)

// Scratch for per-node partial dot products (no cudaMalloc allowed).
__device__ float g_d1[N_NODES];
__device__ float g_d2[N_NODES];

// ---------------------------------------------------------------------------
// Kernel 1: per-node dots. d1[n] = dot(h[n], W[0:H]), d2[n] = dot(h[n], W[H:2H])
// One warp per node; each lane handles 4 columns; shfl reduction.
// ---------------------------------------------------------------------------
__global__ void node_dots_kernel(const float* __restrict__ h,
                                 const float* __restrict__ W) {
    int warp = (int)((blockIdx.x * blockDim.x + threadIdx.x) >> 5);
    int lane = threadIdx.x & 31;
    if (warp >= N_NODES) return;

    const float* hr = h + (size_t)warp * H_DIM;
    float s1 = 0.0f, s2 = 0.0f;
#pragma unroll
    for (int i = 0; i < 4; i++) {
        int c = lane + i * 32;
        float hv = __ldg(&hr[c]);
        s1 = fmaf(hv, __ldg(&W[c]), s1);
        s2 = fmaf(hv, __ldg(&W[H_DIM + c]), s2);
    }
#pragma unroll
    for (int off = 16; off; off >>= 1) {
        s1 += __shfl_down_sync(0xffffffffu, s1, off);
        s2 += __shfl_down_sync(0xffffffffu, s2, off);
    }
    if (lane == 0) {
        g_d1[warp] = s1;
        g_d2[warp] = s2;
    }
}

// ---------------------------------------------------------------------------
// Kernel 2: fill the 604 MB output with NEG. This is the HBM-write roofline.
// Grid-stride float4 streaming stores.
// ---------------------------------------------------------------------------
__global__ void fill_kernel(float4* __restrict__ out, size_t n4) {
    size_t i      = (size_t)blockIdx.x * blockDim.x + threadIdx.x;
    size_t stride = (size_t)gridDim.x * blockDim.x;
    const float4 v = make_float4(NEGVAL, NEGVAL, NEGVAL, NEGVAL);
    for (; i < n4; i += stride) {
        __stcs(&out[i], v);   // streaming store: don't pollute L2 with fill data
    }
}

// ---------------------------------------------------------------------------
// Kernel 3: scatter edge values. val = d1[dst] + d2[src] + w*W[2H] + b
// Races on duplicate (dst,src) pairs are benign (see analysis).
// ---------------------------------------------------------------------------
__global__ void scatter_kernel(const int*   __restrict__ src,
                               const int*   __restrict__ dst,
                               const float* __restrict__ wts,
                               const float* __restrict__ W,
                               const float* __restrict__ b,
                               float* __restrict__ out) {
    int e = (int)(blockIdx.x * blockDim.x + threadIdx.x);
    if (e >= E_EDGES) return;
    int s = src[e];
    int d = dst[e];
    float val = g_d1[d] + g_d2[s] + wts[e] * __ldg(&W[2 * H_DIM]) + __ldg(&b[0]);
    out[(size_t)d * N_NODES + s] = val;
}

// ---------------------------------------------------------------------------
// Launch. Input order (metadata): h, sources, dests, weights, W, b
// ---------------------------------------------------------------------------
extern "C" void kernel_launch(void* const* d_in, const int* in_sizes, int n_in,
                              void* d_out, int out_size) {
    const float* h       = (const float*)d_in[0];
    const int*   sources = (const int*)  d_in[1];
    const int*   dests   = (const int*)  d_in[2];
    const float* weights = (const float*)d_in[3];
    const float* W       = (const float*)d_in[4];
    const float* b       = (const float*)d_in[5];
    float*       out     = (float*)d_out;

    // 1) per-node dots: 12288 warps -> 12288*32 threads
    {
        int threads = 256;                      // 8 warps/block
        int blocks  = (N_NODES * 32 + threads - 1) / threads;  // 1536
        node_dots_kernel<<<blocks, threads>>>(h, W);
    }

    // 2) fill 604 MB with NEG
    {
        size_t n4 = ((size_t)N_NODES * N_NODES) / 4;  // 37,748,736 float4s
        int threads = 256;
        int blocks  = 148 * 16;                 // 2368 blocks, grid-stride
        fill_kernel<<<blocks, threads>>>((float4*)out, n4);
    }

    // 3) scatter edges
    {
        int threads = 256;
        int blocks  = (E_EDGES + threads - 1) / threads;  // 1536
        scatter_kernel<<<blocks, threads>>>(sources, dests, weights, W, b, out);
    }
}